// round 6
// baseline (speedup 1.0000x reference)
#include <cuda_runtime.h>

#define B 64
#define H 768
#define E 128

#define KS 12                     // GEMM k-splits (K chunk = 64 floats)
#define NGEMM (KS * 8 * 2)        // 192 GEMM blocks, bids [0,192) — start first
#define NRED 256                  // reduce blocks, bids [192,448), 32 KB each
#define GRID (NGEMM + NRED)       // 448  (< 148*4 -> single wave)
#define NCOMB 16                  // combiners = last 16 blocks

__device__ float g_S2p[NRED];          // core partials (2 per leading index i)
__device__ float g_P[3][KS][B][E];     // [mat][ks][b][e] gemm partials
__device__ unsigned g_arrive;          // zero-init; self-resetting per launch
__device__ unsigned g_done2;

__global__ void __launch_bounds__(256)
k_all(const float* __restrict__ core,
      const float* __restrict__ hs, const float* __restrict__ rs,
      const float* __restrict__ ts, const float* __restrict__ we,
      const float* __restrict__ wr, const float* __restrict__ be,
      const float* __restrict__ br, float* __restrict__ out) {
    // 18.4 KB total -> >=5 blocks/SM by smem
    __shared__ float4 s_src[3][32][9];   // [mat][b][k4 (8 + swizzle pad)]
    __shared__ float4 s_w[2][16][9];     // [We/Wr][e][k4]

    const int bid = blockIdx.x;
    const int tid = threadIdx.x;

    if (bid < NGEMM) {
        // ---- triple GEMM: 32b x 16e x 64k tile, two 32-float K stages ------
        const int ks = bid % KS, ec = (bid / KS) & 7, bg = bid / (KS * 8);
        const int b0 = bg * 32, e0 = ec * 16;
        const int c0 = ks * 16;  // float4 col offset of this 64-float chunk

        const float4* g0 = reinterpret_cast<const float4*>(hs);
        const float4* g1 = reinterpret_cast<const float4*>(rs);
        const float4* g2 = reinterpret_cast<const float4*>(ts);
        const float4* gwe = reinterpret_cast<const float4*>(we);
        const float4* gwr = reinterpret_cast<const float4*>(wr);

        const int te = tid & 15;   // e within tile
        const int tb = tid >> 4;   // b pair within tile
        const int ba = 2 * tb, bb = ba + 1;

        float h0 = 0.f, h1 = 0.f, r0 = 0.f, r1 = 0.f, t0 = 0.f, t1 = 0.f;

#pragma unroll
        for (int st = 0; st < 2; st++) {
            const int cs = c0 + st * 8;
            if (st > 0) __syncthreads();
            // src tiles: 32 rows x 8 float4 per mat; 256 threads -> 1 per mat
            {
                const int row = tid >> 3, c4 = tid & 7;
                const size_t gidx = (size_t)(b0 + row) * 192 + cs + c4;
                const int sc = c4 ^ (row & 7);
                s_src[0][row][sc] = g0[gidx];
                s_src[1][row][sc] = g1[gidx];
                s_src[2][row][sc] = g2[gidx];
            }
            // W tiles: 16 rows x 8 float4 each; half the threads per matrix
            {
                const int m = tid >> 7;            // 0 -> We, 1 -> Wr
                const int r = (tid & 127) >> 3, c4 = tid & 7;
                const size_t gidx = (size_t)(e0 + r) * 192 + cs + c4;
                const int sc = c4 ^ (r & 7);
                s_w[m][r][sc] = m ? gwr[gidx] : gwe[gidx];
            }
            __syncthreads();

#pragma unroll
            for (int k4 = 0; k4 < 8; k4++) {
                const float4 vwe = s_w[0][te][k4 ^ (te & 7)];
                const float4 vwr = s_w[1][te][k4 ^ (te & 7)];
                const int sa = k4 ^ (ba & 7), sb = k4 ^ (bb & 7);
                float4 a, c;
                a = s_src[0][ba][sa]; c = s_src[0][bb][sb];
                h0 += vwe.x * a.x + vwe.y * a.y + vwe.z * a.z + vwe.w * a.w;
                h1 += vwe.x * c.x + vwe.y * c.y + vwe.z * c.z + vwe.w * c.w;
                a = s_src[1][ba][sa]; c = s_src[1][bb][sb];
                r0 += vwr.x * a.x + vwr.y * a.y + vwr.z * a.z + vwr.w * a.w;
                r1 += vwr.x * c.x + vwr.y * c.y + vwr.z * c.z + vwr.w * c.w;
                a = s_src[2][ba][sa]; c = s_src[2][bb][sb];
                t0 += vwe.x * a.x + vwe.y * a.y + vwe.z * a.z + vwe.w * a.w;
                t1 += vwe.x * c.x + vwe.y * c.y + vwe.z * c.z + vwe.w * c.w;
            }
        }

        const int bga = b0 + ba, bgb = b0 + bb;
        const int e = e0 + te;
        g_P[0][ks][bga][e] = h0;  g_P[0][ks][bgb][e] = h1;
        g_P[1][ks][bga][e] = r0;  g_P[1][ks][bgb][e] = r1;
        g_P[2][ks][bga][e] = t0;  g_P[2][ks][bgb][e] = t1;
    } else {
        // ---- core reduction: 32 KB chunk, 8 explicit independent loads -----
        const int rb = bid - NGEMM;
        const float4* src = reinterpret_cast<const float4*>(core) + (size_t)rb * 2048;
        const float4 v0 = __ldg(src + tid);
        const float4 v1 = __ldg(src + tid + 256);
        const float4 v2 = __ldg(src + tid + 512);
        const float4 v3 = __ldg(src + tid + 768);
        const float4 v4 = __ldg(src + tid + 1024);
        const float4 v5 = __ldg(src + tid + 1280);
        const float4 v6 = __ldg(src + tid + 1536);
        const float4 v7 = __ldg(src + tid + 1792);
        float s = ((((v0.x + v0.y) + (v0.z + v0.w)) + ((v1.x + v1.y) + (v1.z + v1.w)))
                +  (((v2.x + v2.y) + (v2.z + v2.w)) + ((v3.x + v3.y) + (v3.z + v3.w))))
                + ((((v4.x + v4.y) + (v4.z + v4.w)) + ((v5.x + v5.y) + (v5.z + v5.w)))
                +  (((v6.x + v6.y) + (v6.z + v6.w)) + ((v7.x + v7.y) + (v7.z + v7.w))));
#pragma unroll
        for (int o = 16; o > 0; o >>= 1) s += __shfl_xor_sync(0xffffffffu, s, o);
        float* ws = reinterpret_cast<float*>(s_w);
        if ((tid & 31) == 0) ws[tid >> 5] = s;
        __syncthreads();
        if (tid == 0) {
            float tot = 0.f;
#pragma unroll
            for (int w = 0; w < 8; w++) tot += ws[w];
            g_S2p[rb] = tot;
        }
    }

    // ---------------- arrive (every block) --------------------------------
    __threadfence();
    __syncthreads();
    if (tid == 0) atomicAdd(&g_arrive, 1u);

    if (bid < GRID - NCOMB) return;

    // ---------------- combine (last 16 blocks, 4 b-rows each) -------------
    if (tid == 0) {
        volatile unsigned* p = &g_arrive;
        while (*p < GRID) __nanosleep(32);
    }
    __syncthreads();
    __threadfence();

    const int cb = bid - (GRID - NCOMB);          // 0..15
    float* sc = reinterpret_cast<float*>(s_src);  // cross-warp scratch
#pragma unroll
    for (int pass = 0; pass < 2; pass++) {
        const int g = tid >> 7;                   // row group 0/1 in block
        const int b = cb * 4 + pass * 2 + g;
        const int e = tid & 127;

        float h = 0.f, r = 0.f, t = 0.f;
#pragma unroll
        for (int k = 0; k < KS; k++) {
            h += g_P[0][k][b][e];
            r += g_P[1][k][b][e];
            t += g_P[2][k][b][e];
        }
        const float bias_e = be[e], bias_r = br[e];
        const float s2 = g_S2p[2 * e] + g_S2p[2 * e + 1];
        float v = (h + bias_e) * (r + bias_r) * (t + bias_e) * s2;
#pragma unroll
        for (int o = 16; o > 0; o >>= 1) v += __shfl_xor_sync(0xffffffffu, v, o);
        if ((tid & 31) == 0) sc[tid >> 5] = v;
        __syncthreads();
        if ((tid & 127) == 0) {
            const int w0 = g * 4;
            out[b] = -((sc[w0] + sc[w0 + 1]) + (sc[w0 + 2] + sc[w0 + 3]));
        }
        __syncthreads();
    }

    if (tid == 0) {
        const unsigned t = atomicAdd(&g_done2, 1u);
        if (t == NCOMB - 1) {          // last combiner resets for next replay
            g_arrive = 0u;
            __threadfence();
            g_done2 = 0u;
        }
    }
}

// ---------------------------------------------------------------------------
extern "C" void kernel_launch(void* const* d_in, const int* in_sizes, int n_in,
                              void* d_out, int out_size) {
    const float* head = (const float*)d_in[0];
    const float* rel  = (const float*)d_in[1];
    const float* tail = (const float*)d_in[2];
    const float* We   = (const float*)d_in[3];
    const float* be   = (const float*)d_in[4];
    const float* Wr   = (const float*)d_in[5];
    const float* br   = (const float*)d_in[6];
    const float* core = (const float*)d_in[7];
    float* out = (float*)d_out;

    k_all<<<GRID, 256>>>(core, head, rel, tail, We, Wr, be, br, out);
}

// round 7
// speedup vs baseline: 1.3170x; 1.3170x over previous
#include <cuda_runtime.h>

#define B 64
#define H 768
#define E 128

#define KS 12                     // GEMM k-splits (K chunk = 64 floats)
#define NGEMM (KS * 8 * 2)        // 192 GEMM blocks, bids [0,192) — start first
#define NRED 128                  // reduce blocks, bids [192,320): one core row i each
#define GRID (NGEMM + NRED)       // 320  (fits one wave even at 3 blocks/SM)
#define NCOMB 16                  // combiners = last 16 blocks

__device__ float g_S2p[NRED];          // S2[i] final (one block per i)
__device__ float g_P[3][KS][B][E];     // [mat][ks][b][e] gemm partials
__device__ unsigned g_arrive;          // zero-init; self-resetting per launch
__device__ unsigned g_done2;

// ---- packed f32x2 helpers (SASS FFMA2/FADD2 via PTX only) ------------------
__device__ __forceinline__ void fma2(unsigned long long& d,
                                     unsigned long long a, unsigned long long b) {
    asm("fma.rn.f32x2 %0, %1, %2, %0;" : "+l"(d) : "l"(a), "l"(b));
}
__device__ __forceinline__ unsigned long long add2(unsigned long long a,
                                                   unsigned long long b) {
    unsigned long long d;
    asm("add.rn.f32x2 %0, %1, %2;" : "=l"(d) : "l"(a), "l"(b));
    return d;
}
__device__ __forceinline__ float lohi_sum(unsigned long long p) {
    unsigned lo, hi;
    asm("mov.b64 {%0, %1}, %2;" : "=r"(lo), "=r"(hi) : "l"(p));
    return __uint_as_float(lo) + __uint_as_float(hi);
}
union U4 { float4 f; unsigned long long u[2]; };

__global__ void __launch_bounds__(256)
k_all(const float* __restrict__ core,
      const float* __restrict__ hs, const float* __restrict__ rs,
      const float* __restrict__ ts, const float* __restrict__ we,
      const float* __restrict__ wr, const float* __restrict__ be,
      const float* __restrict__ br, float* __restrict__ out) {
    __shared__ float4 s_src[3][32][18];  // gemm src tiles (swizzled)
    __shared__ float4 s_w[2][16][18];    // gemm We/Wr tiles

    const int bid = blockIdx.x;
    const int tid = threadIdx.x;

    if (bid < NGEMM) {
        // ------- triple GEMM (R2 proven, unstaged): 32b x 16e x 64k tile ----
        const int ks = bid % KS, ec = (bid / KS) & 7, bg = bid / (KS * 8);
        const int b0 = bg * 32, e0 = ec * 16;
        const int c0 = ks * 16;  // float4 col offset (64-float K chunk)

        const float4* g0 = reinterpret_cast<const float4*>(hs);
        const float4* g1 = reinterpret_cast<const float4*>(rs);
        const float4* g2 = reinterpret_cast<const float4*>(ts);
#pragma unroll
        for (int i = tid; i < 512; i += 256) {
            const int row = i >> 4, c4 = i & 15;
            const size_t gidx = (size_t)(b0 + row) * 192 + c0 + c4;
            const int sc = c4 ^ (row & 7);
            s_src[0][row][sc] = g0[gidx];
            s_src[1][row][sc] = g1[gidx];
            s_src[2][row][sc] = g2[gidx];
        }
        {
            const int row = tid >> 4, c4 = tid & 15;
            const size_t gidx = (size_t)(e0 + row) * 192 + c0 + c4;
            const int sc = c4 ^ (row & 7);
            s_w[0][row][sc] = reinterpret_cast<const float4*>(we)[gidx];
            s_w[1][row][sc] = reinterpret_cast<const float4*>(wr)[gidx];
        }
        __syncthreads();

        const int te = tid & 15;   // e within tile
        const int tb = tid >> 4;   // b pair within tile
        const int ba = 2 * tb, bb = ba + 1;

        unsigned long long h0p = 0ull, h1p = 0ull, r0p = 0ull, r1p = 0ull;
        unsigned long long t0p = 0ull, t1p = 0ull;
#pragma unroll
        for (int k4 = 0; k4 < 16; k4++) {
            U4 vwe, vwr, a, c;
            vwe.f = s_w[0][te][k4 ^ (te & 7)];
            vwr.f = s_w[1][te][k4 ^ (te & 7)];
            const int sa = k4 ^ (ba & 7), sb = k4 ^ (bb & 7);
            a.f = s_src[0][ba][sa]; c.f = s_src[0][bb][sb];
            fma2(h0p, vwe.u[0], a.u[0]); fma2(h0p, vwe.u[1], a.u[1]);
            fma2(h1p, vwe.u[0], c.u[0]); fma2(h1p, vwe.u[1], c.u[1]);
            a.f = s_src[1][ba][sa]; c.f = s_src[1][bb][sb];
            fma2(r0p, vwr.u[0], a.u[0]); fma2(r0p, vwr.u[1], a.u[1]);
            fma2(r1p, vwr.u[0], c.u[0]); fma2(r1p, vwr.u[1], c.u[1]);
            a.f = s_src[2][ba][sa]; c.f = s_src[2][bb][sb];
            fma2(t0p, vwe.u[0], a.u[0]); fma2(t0p, vwe.u[1], a.u[1]);
            fma2(t1p, vwe.u[0], c.u[0]); fma2(t1p, vwe.u[1], c.u[1]);
        }

        const int bga = b0 + ba, bgb = b0 + bb;
        const int e = e0 + te;
        g_P[0][ks][bga][e] = lohi_sum(h0p);  g_P[0][ks][bgb][e] = lohi_sum(h1p);
        g_P[1][ks][bga][e] = lohi_sum(r0p);  g_P[1][ks][bgb][e] = lohi_sum(r1p);
        g_P[2][ks][bga][e] = lohi_sum(t0p);  g_P[2][ks][bgb][e] = lohi_sum(t1p);
    } else {
        // ------- core reduction: block rb reduces core[rb,:,:] (64 KB) ------
        const int rb = bid - NGEMM;
        const float4* src = reinterpret_cast<const float4*>(core) + (size_t)rb * 4096;
        U4 v[16];
#pragma unroll
        for (int i = 0; i < 16; i++) v[i].f = __ldg(src + tid + i * 256);
        // two f32x2 chains for ILP, then merge
        unsigned long long sA = add2(v[0].u[0], v[0].u[1]);
        unsigned long long sB = add2(v[1].u[0], v[1].u[1]);
#pragma unroll
        for (int i = 2; i < 16; i += 2) {
            sA = add2(sA, add2(v[i].u[0], v[i].u[1]));
            sB = add2(sB, add2(v[i + 1].u[0], v[i + 1].u[1]));
        }
        float s = lohi_sum(add2(sA, sB));
#pragma unroll
        for (int o = 16; o > 0; o >>= 1) s += __shfl_xor_sync(0xffffffffu, s, o);
        float* ws = reinterpret_cast<float*>(s_w);
        if ((tid & 31) == 0) ws[tid >> 5] = s;
        __syncthreads();
        if (tid == 0) {
            float tot = 0.f;
#pragma unroll
            for (int w = 0; w < 8; w++) tot += ws[w];
            g_S2p[rb] = tot;
        }
    }

    // ---------------- arrive (every block) --------------------------------
    __threadfence();
    __syncthreads();
    if (tid == 0) atomicAdd(&g_arrive, 1u);

    if (bid < GRID - NCOMB) return;

    // ---------------- combine (last 16 blocks, 4 b-rows each) -------------
    if (tid == 0) {
        volatile unsigned* p = &g_arrive;
        while (*p < GRID) __nanosleep(32);
    }
    __syncthreads();
    __threadfence();

    const int cb = bid - (GRID - NCOMB);          // 0..15
    float* sc = reinterpret_cast<float*>(s_src);  // cross-warp scratch
#pragma unroll
    for (int pass = 0; pass < 2; pass++) {
        const int g = tid >> 7;                   // row group 0/1 in block
        const int b = cb * 4 + pass * 2 + g;
        const int e = tid & 127;

        float h = 0.f, r = 0.f, t = 0.f;
#pragma unroll
        for (int k = 0; k < KS; k++) {
            h += g_P[0][k][b][e];
            r += g_P[1][k][b][e];
            t += g_P[2][k][b][e];
        }
        const float bias_e = be[e], bias_r = br[e];
        const float s2 = g_S2p[e];
        float v = (h + bias_e) * (r + bias_r) * (t + bias_e) * s2;
#pragma unroll
        for (int o = 16; o > 0; o >>= 1) v += __shfl_xor_sync(0xffffffffu, v, o);
        if ((tid & 31) == 0) sc[tid >> 5] = v;
        __syncthreads();
        if ((tid & 127) == 0) {
            const int w0 = g * 4;
            out[b] = -((sc[w0] + sc[w0 + 1]) + (sc[w0 + 2] + sc[w0 + 3]));
        }
        __syncthreads();
    }

    if (tid == 0) {
        const unsigned t = atomicAdd(&g_done2, 1u);
        if (t == NCOMB - 1) {          // last combiner resets for next replay
            g_arrive = 0u;
            __threadfence();
            g_done2 = 0u;
        }
    }
}

// ---------------------------------------------------------------------------
extern "C" void kernel_launch(void* const* d_in, const int* in_sizes, int n_in,
                              void* d_out, int out_size) {
    const float* head = (const float*)d_in[0];
    const float* rel  = (const float*)d_in[1];
    const float* tail = (const float*)d_in[2];
    const float* We   = (const float*)d_in[3];
    const float* be   = (const float*)d_in[4];
    const float* Wr   = (const float*)d_in[5];
    const float* br   = (const float*)d_in[6];
    const float* core = (const float*)d_in[7];
    float* out = (float*)d_out;

    k_all<<<GRID, 256>>>(core, head, rel, tail, We, Wr, be, br, out);
}

// round 8
// speedup vs baseline: 1.3434x; 1.0201x over previous
#include <cuda_runtime.h>

#define B 64
#define H 768
#define E 128

#define KS 12                     // GEMM k-splits (K chunk = 64 floats)
#define NGEMM (KS * 8 * 2)        // 192 GEMM blocks, bids [0,192) — start first
#define NRED 256                  // reduce blocks, bids [192,448), 32 KB, MLP=8
#define GRID (NGEMM + NRED)       // 448; capacity >= 5 blk/SM * 148 = 740 -> 1 wave
#define NCOMB 32                  // combiners = last 32 blocks, 2 b-rows each

__device__ float g_S2p[NRED];          // core partials (2 per leading index i)
__device__ float g_P[3][KS][B][E];     // [mat][ks][b][e] gemm partials
__device__ unsigned g_arrive;          // zero-init; self-resetting per launch
__device__ unsigned g_done2;

__global__ void __launch_bounds__(256)
k_all(const float* __restrict__ core,
      const float* __restrict__ hs, const float* __restrict__ rs,
      const float* __restrict__ ts, const float* __restrict__ we,
      const float* __restrict__ wr, const float* __restrict__ be,
      const float* __restrict__ br, float* __restrict__ out) {
    __shared__ float4 s_src[3][32][18];  // gemm src tiles (swizzled) / scratch
    __shared__ float4 s_w[2][16][18];    // gemm We/Wr tiles / reduce scratch

    const int bid = blockIdx.x;
    const int tid = threadIdx.x;

    if (bid < NGEMM) {
        // ------- triple GEMM (R2 proven, unstaged): 32b x 16e x 64k tile ----
        const int ks = bid % KS, ec = (bid / KS) & 7, bg = bid / (KS * 8);
        const int b0 = bg * 32, e0 = ec * 16;
        const int c0 = ks * 16;  // float4 col offset (64-float K chunk)

        const float4* g0 = reinterpret_cast<const float4*>(hs);
        const float4* g1 = reinterpret_cast<const float4*>(rs);
        const float4* g2 = reinterpret_cast<const float4*>(ts);
#pragma unroll
        for (int i = tid; i < 512; i += 256) {
            const int row = i >> 4, c4 = i & 15;
            const size_t gidx = (size_t)(b0 + row) * 192 + c0 + c4;
            const int sc = c4 ^ (row & 7);
            s_src[0][row][sc] = g0[gidx];
            s_src[1][row][sc] = g1[gidx];
            s_src[2][row][sc] = g2[gidx];
        }
        {
            const int row = tid >> 4, c4 = tid & 15;
            const size_t gidx = (size_t)(e0 + row) * 192 + c0 + c4;
            const int sc = c4 ^ (row & 7);
            s_w[0][row][sc] = reinterpret_cast<const float4*>(we)[gidx];
            s_w[1][row][sc] = reinterpret_cast<const float4*>(wr)[gidx];
        }
        __syncthreads();

        const int te = tid & 15;   // e within tile
        const int tb = tid >> 4;   // b pair within tile
        const int ba = 2 * tb, bb = ba + 1;

        float h0 = 0.f, h1 = 0.f, r0 = 0.f, r1 = 0.f, t0 = 0.f, t1 = 0.f;
#pragma unroll
        for (int k4 = 0; k4 < 16; k4++) {
            const float4 vwe = s_w[0][te][k4 ^ (te & 7)];
            const float4 vwr = s_w[1][te][k4 ^ (te & 7)];
            const int sa = k4 ^ (ba & 7), sb = k4 ^ (bb & 7);
            float4 a, c;
            a = s_src[0][ba][sa]; c = s_src[0][bb][sb];
            h0 += vwe.x * a.x + vwe.y * a.y + vwe.z * a.z + vwe.w * a.w;
            h1 += vwe.x * c.x + vwe.y * c.y + vwe.z * c.z + vwe.w * c.w;
            a = s_src[1][ba][sa]; c = s_src[1][bb][sb];
            r0 += vwr.x * a.x + vwr.y * a.y + vwr.z * a.z + vwr.w * a.w;
            r1 += vwr.x * c.x + vwr.y * c.y + vwr.z * c.z + vwr.w * c.w;
            a = s_src[2][ba][sa]; c = s_src[2][bb][sb];
            t0 += vwe.x * a.x + vwe.y * a.y + vwe.z * a.z + vwe.w * a.w;
            t1 += vwe.x * c.x + vwe.y * c.y + vwe.z * c.z + vwe.w * c.w;
        }

        const int bga = b0 + ba, bgb = b0 + bb;
        const int e = e0 + te;
        g_P[0][ks][bga][e] = h0;  g_P[0][ks][bgb][e] = h1;
        g_P[1][ks][bga][e] = r0;  g_P[1][ks][bgb][e] = r1;
        g_P[2][ks][bga][e] = t0;  g_P[2][ks][bgb][e] = t1;
    } else {
        // ------- core reduction (R2 proven): 32 KB chunk, 8 explicit loads --
        const int rb = bid - NGEMM;
        const float4* src = reinterpret_cast<const float4*>(core) + (size_t)rb * 2048;
        const float4 v0 = __ldg(src + tid);
        const float4 v1 = __ldg(src + tid + 256);
        const float4 v2 = __ldg(src + tid + 512);
        const float4 v3 = __ldg(src + tid + 768);
        const float4 v4 = __ldg(src + tid + 1024);
        const float4 v5 = __ldg(src + tid + 1280);
        const float4 v6 = __ldg(src + tid + 1536);
        const float4 v7 = __ldg(src + tid + 1792);
        float s = ((((v0.x + v0.y) + (v0.z + v0.w)) + ((v1.x + v1.y) + (v1.z + v1.w)))
                +  (((v2.x + v2.y) + (v2.z + v2.w)) + ((v3.x + v3.y) + (v3.z + v3.w))))
                + ((((v4.x + v4.y) + (v4.z + v4.w)) + ((v5.x + v5.y) + (v5.z + v5.w)))
                +  (((v6.x + v6.y) + (v6.z + v6.w)) + ((v7.x + v7.y) + (v7.z + v7.w))));
#pragma unroll
        for (int o = 16; o > 0; o >>= 1) s += __shfl_xor_sync(0xffffffffu, s, o);
        float* ws = reinterpret_cast<float*>(s_w);
        if ((tid & 31) == 0) ws[tid >> 5] = s;
        __syncthreads();
        if (tid == 0) {
            float tot = 0.f;
#pragma unroll
            for (int w = 0; w < 8; w++) tot += ws[w];
            g_S2p[rb] = tot;
        }
    }

    // ---------------- arrive (every block) --------------------------------
    __threadfence();
    __syncthreads();
    if (tid == 0) atomicAdd(&g_arrive, 1u);

    if (bid < GRID - NCOMB) return;

    // ---------------- combine (last 32 blocks, 2 b-rows each) -------------
    if (tid == 0) {
        volatile unsigned* p = &g_arrive;
        while (*p < GRID) __nanosleep(32);
    }
    __syncthreads();
    __threadfence();

    const int cb = bid - (GRID - NCOMB);          // 0..31
    float* sx = reinterpret_cast<float*>(s_src);  // scratch: 3*128 + 4 floats
    const int e = tid & 127;
    const int half = tid >> 7;                    // ks half: 0 -> 0..5, 1 -> 6..11
    const int k0 = half * 6;

#pragma unroll
    for (int pass = 0; pass < 2; pass++) {
        const int b = cb * 2 + pass;

        float h = 0.f, r = 0.f, t = 0.f;
#pragma unroll
        for (int k = 0; k < 6; k++) {
            h += g_P[0][k0 + k][b][e];
            r += g_P[1][k0 + k][b][e];
            t += g_P[2][k0 + k][b][e];
        }
        if (half == 1) { sx[e] = h; sx[128 + e] = r; sx[256 + e] = t; }
        __syncthreads();
        if (half == 0) {
            h += sx[e]; r += sx[128 + e]; t += sx[256 + e];
            const float bias_e = be[e], bias_r = br[e];
            const float s2 = g_S2p[2 * e] + g_S2p[2 * e + 1];
            float v = (h + bias_e) * (r + bias_r) * (t + bias_e) * s2;
#pragma unroll
            for (int o = 16; o > 0; o >>= 1) v += __shfl_xor_sync(0xffffffffu, v, o);
            if ((e & 31) == 0) sx[384 + (e >> 5)] = v;
        }
        __syncthreads();
        if (tid == 0)
            out[b] = -((sx[384] + sx[385]) + (sx[386] + sx[387]));
        __syncthreads();
    }

    if (tid == 0) {
        const unsigned t = atomicAdd(&g_done2, 1u);
        if (t == NCOMB - 1) {          // last combiner resets for next replay
            g_arrive = 0u;
            __threadfence();
            g_done2 = 0u;
        }
    }
}

// ---------------------------------------------------------------------------
extern "C" void kernel_launch(void* const* d_in, const int* in_sizes, int n_in,
                              void* d_out, int out_size) {
    const float* head = (const float*)d_in[0];
    const float* rel  = (const float*)d_in[1];
    const float* tail = (const float*)d_in[2];
    const float* We   = (const float*)d_in[3];
    const float* be   = (const float*)d_in[4];
    const float* Wr   = (const float*)d_in[5];
    const float* br   = (const float*)d_in[6];
    const float* core = (const float*)d_in[7];
    float* out = (float*)d_out;

    k_all<<<GRID, 256>>>(core, head, rel, tail, We, Wr, be, br, out);
}